// round 5
// baseline (speedup 1.0000x reference)
#include <cuda_runtime.h>
#include <math.h>

// Problem constants
#define BB   8
#define AA   192
#define DD   128
#define RELN 5
#define HH   128
#define EE   (BB*AA*AA)   // 294912 edges
#define KK   384          // K-dim of i/j precompute GEMM (3*D)

// Scratch (no cudaMalloc allowed)
__device__ float g_pre_i[BB*AA*HH];   // f(i) partial pre-activation
__device__ float g_pre_j[BB*AA*HH];   // f(j) partial pre-activation
__device__ float g_pre_g[BB*HH];      // graph-context partial + b1
__device__ float g_W1T[256*KK];       // transposed W1 i/j slices: [c][d], c<128 -> i, c>=128 -> j

// ---------------------------------------------------------------------------
// Kernel 1 (fused): transpose W1 rows 0..767 into W1T[c][d]  +  pre_g.
// Blocks 0..383: transpose (coalesced reads, scattered 4B writes).
// Blocks 384..391: pre_g for batch b = blockIdx-384 (threads 0..127).
// ---------------------------------------------------------------------------
__global__ __launch_bounds__(256) void prep_kernel(
    const float* __restrict__ W1, const float* __restrict__ gc,
    const float* __restrict__ b1)
{
    if (blockIdx.x < 384) {
        // gid over (row, k), row in [0,768), k in [0,128)
        const int gid = blockIdx.x * 256 + threadIdx.x;
        const int row = gid >> 7;
        const int k   = gid & 127;
        const int s     = row >> 8;         // 0..2
        const int rem   = row & 255;
        const int which = rem >> 7;         // 0 -> i, 1 -> j
        const int dl    = rem & 127;
        const int d     = s * 128 + dl;     // 0..383
        const int c     = which * 128 + k;  // 0..255
        g_W1T[c * KK + d] = W1[row * HH + k];
    } else {
        const int b = blockIdx.x - 384;
        const int k = threadIdx.x;
        if (k < HH) {
            __shared__ float gs[DD];
            gs[k] = gc[b * DD + k];
            __syncthreads();
            float acc = b1[k];
#pragma unroll 8
            for (int d = 0; d < DD; d++)
                acc = fmaf(gs[d], W1[(6 * DD + RELN + d) * HH + k], acc);
            g_pre_g[b * HH + k] = acc;
        } else {
            __syncthreads();
        }
    }
}

// ---------------------------------------------------------------------------
// Kernel 2: precompute pre_i / pre_j.
// Grid 384 blocks x 256 threads; each block does 4 rows x 256 output cols.
// Thread c (= tid) computes channel (c&127) of (c<128 ? pre_i : pre_j) for
// its block's 4 rows.  Weights read as float4 from W1T, x from smem float4.
// ---------------------------------------------------------------------------
#define PRE_ROWS 4
__global__ __launch_bounds__(256) void precompute_ij(
    const float* __restrict__ coord, const float* __restrict__ goal,
    const float* __restrict__ frontier)
{
    __shared__ __align__(16) float xs[PRE_ROWS][KK];
    const int row0 = blockIdx.x * PRE_ROWS;
    const int tid  = threadIdx.x;

    for (int idx = tid; idx < PRE_ROWS * KK; idx += 256) {
        int rr = idx / KK, cc = idx % KK;
        int s = cc >> 7, d = cc & 127;
        const float* src = (s == 0) ? coord : ((s == 1) ? goal : frontier);
        xs[rr][cc] = src[(row0 + rr) * DD + d];
    }
    __syncthreads();

    const float4* wrow = (const float4*)&g_W1T[tid * KK];
    const float4* x0 = (const float4*)xs[0];
    const float4* x1 = (const float4*)xs[1];
    const float4* x2 = (const float4*)xs[2];
    const float4* x3 = (const float4*)xs[3];

    float a0 = 0.f, a1 = 0.f, a2 = 0.f, a3 = 0.f;
#pragma unroll 4
    for (int t = 0; t < KK / 4; t++) {
        const float4 w = wrow[t];
        float4 x;
        x = x0[t];
        a0 = fmaf(w.x, x.x, a0); a0 = fmaf(w.y, x.y, a0);
        a0 = fmaf(w.z, x.z, a0); a0 = fmaf(w.w, x.w, a0);
        x = x1[t];
        a1 = fmaf(w.x, x.x, a1); a1 = fmaf(w.y, x.y, a1);
        a1 = fmaf(w.z, x.z, a1); a1 = fmaf(w.w, x.w, a1);
        x = x2[t];
        a2 = fmaf(w.x, x.x, a2); a2 = fmaf(w.y, x.y, a2);
        a2 = fmaf(w.z, x.z, a2); a2 = fmaf(w.w, x.w, a2);
        x = x3[t];
        a3 = fmaf(w.x, x.x, a3); a3 = fmaf(w.y, x.y, a3);
        a3 = fmaf(w.z, x.z, a3); a3 = fmaf(w.w, x.w, a3);
    }

    float* dst = (tid < 128) ? g_pre_i : g_pre_j;
    const int k = tid & 127;
    dst[(row0 + 0) * HH + k] = a0;
    dst[(row0 + 1) * HH + k] = a1;
    dst[(row0 + 2) * HH + k] = a2;
    dst[(row0 + 3) * HH + k] = a3;
}

// ---------------------------------------------------------------------------
// Kernel 3: edge MLP + masked softmax.  One block per (b,i); 8 warps, each
// warp owns one j at a time.  Lane handles 4 CONSECUTIVE channels
// (k = 4*lane..4*lane+3) so all per-channel constants are register-resident
// float4s and pre_j is a single LDG.128 per j.
// ---------------------------------------------------------------------------
__global__ __launch_bounds__(256) void edge_kernel(
    const float* __restrict__ rel,        // [B,A,A,5]
    const int* __restrict__ adj,          // [B,A,A] bool as int32
    const float* __restrict__ base,       // [B,A,A]
    const float* __restrict__ W1,
    const float* __restrict__ W2,         // [H,1]
    const float* __restrict__ b2,         // [1]
    float* __restrict__ out)              // [3*E]: weights | score(masked) | learned
{
    const int i = blockIdx.x, b = blockIdx.y;
    const int tid  = threadIdx.x;
    const int wid  = tid >> 5, lane = tid & 31;

    __shared__ float scores_s[AA];
    __shared__ float red_s[8];
    __shared__ float mx_s, S_s, sum2_s;

    // Register-resident per-channel constants (channels 4*lane .. 4*lane+3)
    const float4 pi4 = ((const float4*)&g_pre_i[(b * AA + i) * HH])[lane];
    const float4 pg4 = ((const float4*)&g_pre_g[b * HH])[lane];
    const float4 bias = make_float4(pi4.x + pg4.x, pi4.y + pg4.y,
                                    pi4.z + pg4.z, pi4.w + pg4.w);
    const float4 w2v = ((const float4*)W2)[lane];
    float4 wr[RELN];
#pragma unroll
    for (int r = 0; r < RELN; r++)
        wr[r] = ((const float4*)&W1[(6 * DD + r) * HH])[lane];
    const float b2v = b2[0];

    const int rowbase = (b * AA + i) * AA;
    const float4* prej4 = (const float4*)g_pre_j;

#pragma unroll 2
    for (int j = wid; j < AA; j += 8) {
        const int e = rowbase + j;
        const float4 pj = prej4[(b * AA + j) * (HH / 4) + lane];
        const float* rf = &rel[(long)e * RELN];
        const float r0 = rf[0], r1 = rf[1], r2 = rf[2], r3 = rf[3], r4 = rf[4];

        float hx = bias.x + pj.x, hy = bias.y + pj.y;
        float hz = bias.z + pj.z, hw = bias.w + pj.w;
        hx = fmaf(r0, wr[0].x, hx); hy = fmaf(r0, wr[0].y, hy);
        hz = fmaf(r0, wr[0].z, hz); hw = fmaf(r0, wr[0].w, hw);
        hx = fmaf(r1, wr[1].x, hx); hy = fmaf(r1, wr[1].y, hy);
        hz = fmaf(r1, wr[1].z, hz); hw = fmaf(r1, wr[1].w, hw);
        hx = fmaf(r2, wr[2].x, hx); hy = fmaf(r2, wr[2].y, hy);
        hz = fmaf(r2, wr[2].z, hz); hw = fmaf(r2, wr[2].w, hw);
        hx = fmaf(r3, wr[3].x, hx); hy = fmaf(r3, wr[3].y, hy);
        hz = fmaf(r3, wr[3].z, hz); hw = fmaf(r3, wr[3].w, hw);
        hx = fmaf(r4, wr[4].x, hx); hy = fmaf(r4, wr[4].y, hy);
        hz = fmaf(r4, wr[4].z, hz); hw = fmaf(r4, wr[4].w, hw);
        hx = fmaxf(hx, 0.f); hy = fmaxf(hy, 0.f);
        hz = fmaxf(hz, 0.f); hw = fmaxf(hw, 0.f);

        float acc = hx * w2v.x;
        acc = fmaf(hy, w2v.y, acc);
        acc = fmaf(hz, w2v.z, acc);
        acc = fmaf(hw, w2v.w, acc);
#pragma unroll
        for (int o = 16; o > 0; o >>= 1)
            acc += __shfl_xor_sync(0xffffffffu, acc, o);

        if (lane == 0) {
            const float learned = acc + b2v;
            const float sc = base[e] + learned;
            const float sc_masked = adj[e] ? sc : -1e9f;
            out[EE   + e] = sc_masked;   // score (masked, as reference returns)
            out[2*EE + e] = learned;     // learned (unmasked)
            scores_s[j] = sc_masked;
        }
    }
    __syncthreads();

    // ---- masked softmax + adj renorm (matches reference semantics) ----
    float s = (tid < AA) ? scores_s[tid] : -INFINITY;
#pragma unroll
    for (int o = 16; o > 0; o >>= 1)
        s = fmaxf(s, __shfl_xor_sync(0xffffffffu, s, o));
    if (lane == 0) red_s[wid] = s;
    __syncthreads();
    if (tid == 0) {
        float m = red_s[0];
#pragma unroll
        for (int w = 1; w < 8; w++) m = fmaxf(m, red_s[w]);
        mx_s = m;
    }
    __syncthreads();
    const float mx = mx_s;

    float scv = 0.f, ev = 0.f;
    if (tid < AA) {
        scv = scores_s[tid];
        ev  = expf(scv - mx);   // masked (-1e9) underflows to exactly 0
    }
    float t = ev;
#pragma unroll
    for (int o = 16; o > 0; o >>= 1)
        t += __shfl_xor_sync(0xffffffffu, t, o);
    if (lane == 0) red_s[wid] = t;
    __syncthreads();
    if (tid == 0) {
        float sum = 0.f;
#pragma unroll
        for (int w = 0; w < 8; w++) sum += red_s[w];
        S_s = sum;
    }
    __syncthreads();

    float wpre = (tid < AA && scv > -1e8f) ? (ev / S_s) : 0.f;
    t = wpre;
#pragma unroll
    for (int o = 16; o > 0; o >>= 1)
        t += __shfl_xor_sync(0xffffffffu, t, o);
    if (lane == 0) red_s[wid] = t;
    __syncthreads();
    if (tid == 0) {
        float sum = 0.f;
#pragma unroll
        for (int w = 0; w < 8; w++) sum += red_s[w];
        sum2_s = sum;
    }
    __syncthreads();

    if (tid < AA)
        out[rowbase + tid] = wpre / (sum2_s + 1e-8f);
}

// ---------------------------------------------------------------------------
extern "C" void kernel_launch(void* const* d_in, const int* in_sizes, int n_in,
                              void* d_out, int out_size)
{
    const float* coord    = (const float*)d_in[0];
    const float* goal     = (const float*)d_in[1];
    const float* frontier = (const float*)d_in[2];
    const float* rel      = (const float*)d_in[3];
    const int*   adj      = (const int*)d_in[4];
    const float* base     = (const float*)d_in[5];
    const float* gc       = (const float*)d_in[6];
    const float* W1       = (const float*)d_in[7];
    const float* b1       = (const float*)d_in[8];
    const float* W2       = (const float*)d_in[9];
    const float* b2       = (const float*)d_in[10];
    float* out = (float*)d_out;

    prep_kernel<<<392, 256>>>(W1, gc, b1);
    precompute_ij<<<(BB*AA)/PRE_ROWS, 256>>>(coord, goal, frontier);
    dim3 grid(AA, BB);
    edge_kernel<<<grid, 256>>>(rel, adj, base, W1, W2, b2, out);
}

// round 6
// speedup vs baseline: 1.9444x; 1.9444x over previous
#include <cuda_runtime.h>
#include <math.h>

// Problem constants
#define BB   8
#define AA   192
#define DD   128
#define RELN 5
#define HH   128
#define EE   (BB*AA*AA)   // 294912 edges
#define KK   384          // K-dim of i/j precompute GEMM (3*D)

// Scratch (no cudaMalloc allowed)
__device__ float g_pre_i[BB*AA*HH];   // f(i) partial pre-activation
__device__ float g_pre_j[BB*AA*HH];   // f(j) partial pre-activation
__device__ float g_pre_g[BB*HH];      // graph-context partial + b1

// ---------------------------------------------------------------------------
// Kernel 1: precompute pre_i / pre_j  (+ fused pre_g tail blocks).
// Blocks 0..383: GEMM tile = 8 rows x 128 cols.  blockIdx>>1 = row-group,
//   blockIdx&1 = which (0 -> i-slices of W1, 1 -> j-slices).
//   W1 chunks staged in double-buffered smem with coalesced loads (lane = col);
//   x stored as xs[d][row] so the 8 row-values come from two broadcast LDS.128.
// Blocks 384..391: pre_g for batch b = blockIdx-384.
// ---------------------------------------------------------------------------
#define CH   16            // K-chunk size
#define NCH  (KK/CH)       // 24 chunks
#define XPAD 12            // xs row stride in floats (48B -> float4-aligned)

__global__ __launch_bounds__(128) void precompute_kernel(
    const float* __restrict__ coord, const float* __restrict__ goal,
    const float* __restrict__ frontier, const float* __restrict__ gc,
    const float* __restrict__ W1, const float* __restrict__ b1)
{
    __shared__ __align__(16) float xs[KK][XPAD];   // [d][row 0..7]
    __shared__ float ws[2][CH][128];               // staged W1 chunks

    const int tid = threadIdx.x;   // 0..127 == output col k

    if (blockIdx.x >= 384) {
        // ---- pre_g ----
        const int b = blockIdx.x - 384;
        float* gs = &xs[0][0];
        gs[tid] = gc[b * DD + tid];
        __syncthreads();
        float acc = b1[tid];
#pragma unroll 8
        for (int d = 0; d < DD; d++)
            acc = fmaf(gs[d], W1[(6 * DD + RELN + d) * HH + tid], acc);
        g_pre_g[b * HH + tid] = acc;
        return;
    }

    const int row0  = (blockIdx.x >> 1) * 8;
    const int which = blockIdx.x & 1;

    // Load x rows: coalesced global reads, xs[c][rr] smem layout
    for (int idx = tid; idx < 8 * KK; idx += 128) {
        const int rr = idx / KK, c = idx % KK;
        const int s = c >> 7, d = c & 127;
        const float* src = (s == 0) ? coord : ((s == 1) ? goal : frontier);
        xs[c][rr] = src[(row0 + rr) * DD + d];
    }

    // W1 row for logical k-index d:  (d>>7)*256 + which*128 + (d&127)
    const int wofs = which * 128;

    float tmp[CH];
    // prologue: chunk 0
#pragma unroll
    for (int dd = 0; dd < CH; dd++) {
        const int d = dd;
        tmp[dd] = W1[((d >> 7) * 256 + wofs + (d & 127)) * HH + tid];
    }
#pragma unroll
    for (int dd = 0; dd < CH; dd++) ws[0][dd][tid] = tmp[dd];
    __syncthreads();

    float a0 = 0.f, a1 = 0.f, a2 = 0.f, a3 = 0.f;
    float a4 = 0.f, a5 = 0.f, a6 = 0.f, a7 = 0.f;

    for (int c = 0; c < NCH; c++) {
        const int buf = c & 1;
        if (c + 1 < NCH) {
            const int d0 = (c + 1) * CH;
#pragma unroll
            for (int dd = 0; dd < CH; dd++) {
                const int d = d0 + dd;
                tmp[dd] = W1[((d >> 7) * 256 + wofs + (d & 127)) * HH + tid];
            }
        }
        const int d0 = c * CH;
#pragma unroll
        for (int dd = 0; dd < CH; dd++) {
            const float w = ws[buf][dd][tid];
            const float4 xlo = *(const float4*)&xs[d0 + dd][0];
            const float4 xhi = *(const float4*)&xs[d0 + dd][4];
            a0 = fmaf(w, xlo.x, a0); a1 = fmaf(w, xlo.y, a1);
            a2 = fmaf(w, xlo.z, a2); a3 = fmaf(w, xlo.w, a3);
            a4 = fmaf(w, xhi.x, a4); a5 = fmaf(w, xhi.y, a5);
            a6 = fmaf(w, xhi.z, a6); a7 = fmaf(w, xhi.w, a7);
        }
        if (c + 1 < NCH) {
#pragma unroll
            for (int dd = 0; dd < CH; dd++) ws[buf ^ 1][dd][tid] = tmp[dd];
        }
        __syncthreads();
    }

    float* dst = which ? g_pre_j : g_pre_i;
    dst[(row0 + 0) * HH + tid] = a0;
    dst[(row0 + 1) * HH + tid] = a1;
    dst[(row0 + 2) * HH + tid] = a2;
    dst[(row0 + 3) * HH + tid] = a3;
    dst[(row0 + 4) * HH + tid] = a4;
    dst[(row0 + 5) * HH + tid] = a5;
    dst[(row0 + 6) * HH + tid] = a6;
    dst[(row0 + 7) * HH + tid] = a7;
}

// ---------------------------------------------------------------------------
// Kernel 2: edge MLP + masked softmax.  One block per (b, i-pair).
// 8 warps; each warp owns one j at a time, computing BOTH rows i0,i1 from a
// single pre_j float4 load.  rel rows staged in smem.  All mask/base/score
// work is done coalesced in the post phase.
// ---------------------------------------------------------------------------
__global__ __launch_bounds__(256) void edge_kernel(
    const float* __restrict__ rel,        // [B,A,A,5]
    const int* __restrict__ adj,          // [B,A,A] bool as int32
    const float* __restrict__ base,       // [B,A,A]
    const float* __restrict__ W1,
    const float* __restrict__ W2,         // [H,1]
    const float* __restrict__ b2,         // [1]
    float* __restrict__ out)              // [3*E]: weights | score(masked) | learned
{
    const int i0 = blockIdx.x * 2, b = blockIdx.y;
    const int tid  = threadIdx.x;
    const int wid  = tid >> 5, lane = tid & 31;

    __shared__ float rel_s[2][AA][RELN];  // 7.5 KB
    __shared__ float ln_s[2][AA];
    __shared__ float red_s[8];
    __shared__ float mx_s, S_s, sum2_s;

    // stage rel rows for i0, i0+1 (contiguous in memory)
    {
        const float* rbase = rel + (long)(b * AA + i0) * AA * RELN;
        float* rdst = &rel_s[0][0][0];
        for (int idx = tid; idx < 2 * AA * RELN; idx += 256)
            rdst[idx] = rbase[idx];
    }

    // register-resident per-channel constants (channels 4*lane .. 4*lane+3)
    const float4 pg4  = ((const float4*)&g_pre_g[b * HH])[lane];
    const float4 pi0  = ((const float4*)&g_pre_i[(b * AA + i0) * HH])[lane];
    const float4 pi1  = ((const float4*)&g_pre_i[(b * AA + i0 + 1) * HH])[lane];
    const float4 bias0 = make_float4(pi0.x + pg4.x, pi0.y + pg4.y,
                                     pi0.z + pg4.z, pi0.w + pg4.w);
    const float4 bias1 = make_float4(pi1.x + pg4.x, pi1.y + pg4.y,
                                     pi1.z + pg4.z, pi1.w + pg4.w);
    const float4 w2v = ((const float4*)W2)[lane];
    float4 wr[RELN];
#pragma unroll
    for (int r = 0; r < RELN; r++)
        wr[r] = ((const float4*)&W1[(6 * DD + r) * HH])[lane];
    const float b2v = b2[0];

    const float4* prej4 = (const float4*)g_pre_j;
    __syncthreads();

#pragma unroll 2
    for (int j = wid; j < AA; j += 8) {
        const float4 pj = prej4[(b * AA + j) * (HH / 4) + lane];
        float acc0, acc1;
#pragma unroll
        for (int ii = 0; ii < 2; ii++) {
            const float4 bias = ii ? bias1 : bias0;
            const float r0 = rel_s[ii][j][0], r1 = rel_s[ii][j][1];
            const float r2 = rel_s[ii][j][2], r3 = rel_s[ii][j][3];
            const float r4 = rel_s[ii][j][4];
            float hx = bias.x + pj.x, hy = bias.y + pj.y;
            float hz = bias.z + pj.z, hw = bias.w + pj.w;
            hx = fmaf(r0, wr[0].x, hx); hy = fmaf(r0, wr[0].y, hy);
            hz = fmaf(r0, wr[0].z, hz); hw = fmaf(r0, wr[0].w, hw);
            hx = fmaf(r1, wr[1].x, hx); hy = fmaf(r1, wr[1].y, hy);
            hz = fmaf(r1, wr[1].z, hz); hw = fmaf(r1, wr[1].w, hw);
            hx = fmaf(r2, wr[2].x, hx); hy = fmaf(r2, wr[2].y, hy);
            hz = fmaf(r2, wr[2].z, hz); hw = fmaf(r2, wr[2].w, hw);
            hx = fmaf(r3, wr[3].x, hx); hy = fmaf(r3, wr[3].y, hy);
            hz = fmaf(r3, wr[3].z, hz); hw = fmaf(r3, wr[3].w, hw);
            hx = fmaf(r4, wr[4].x, hx); hy = fmaf(r4, wr[4].y, hy);
            hz = fmaf(r4, wr[4].z, hz); hw = fmaf(r4, wr[4].w, hw);
            hx = fmaxf(hx, 0.f); hy = fmaxf(hy, 0.f);
            hz = fmaxf(hz, 0.f); hw = fmaxf(hw, 0.f);
            float acc = hx * w2v.x;
            acc = fmaf(hy, w2v.y, acc);
            acc = fmaf(hz, w2v.z, acc);
            acc = fmaf(hw, w2v.w, acc);
            if (ii) acc1 = acc; else acc0 = acc;
        }
#pragma unroll
        for (int o = 16; o > 0; o >>= 1) {
            acc0 += __shfl_xor_sync(0xffffffffu, acc0, o);
            acc1 += __shfl_xor_sync(0xffffffffu, acc1, o);
        }
        if (lane == 0) {
            ln_s[0][j] = acc0 + b2v;
            ln_s[1][j] = acc1 + b2v;
        }
    }
    __syncthreads();

    // ---- post phase: mask, score outputs, softmax, renorm (per row) ----
#pragma unroll
    for (int ii = 0; ii < 2; ii++) {
        const int rowbase = (b * AA + i0 + ii) * AA;
        float scm = -INFINITY, lv = 0.f;
        if (tid < AA) {
            lv = ln_s[ii][tid];
            const float scu = base[rowbase + tid] + lv;
            scm = adj[rowbase + tid] ? scu : -1e9f;
            out[EE   + rowbase + tid] = scm;   // score (masked, as reference)
            out[2*EE + rowbase + tid] = lv;    // learned (unmasked)
        }
        // block max
        float s = scm;
#pragma unroll
        for (int o = 16; o > 0; o >>= 1)
            s = fmaxf(s, __shfl_xor_sync(0xffffffffu, s, o));
        if (lane == 0) red_s[wid] = s;
        __syncthreads();
        if (tid == 0) {
            float m = red_s[0];
#pragma unroll
            for (int w = 1; w < 8; w++) m = fmaxf(m, red_s[w]);
            mx_s = m;
        }
        __syncthreads();
        const float mx = mx_s;

        const float ev = (tid < AA) ? expf(scm - mx) : 0.f;  // masked -> 0
        float t = ev;
#pragma unroll
        for (int o = 16; o > 0; o >>= 1)
            t += __shfl_xor_sync(0xffffffffu, t, o);
        if (lane == 0) red_s[wid] = t;
        __syncthreads();
        if (tid == 0) {
            float sum = 0.f;
#pragma unroll
            for (int w = 0; w < 8; w++) sum += red_s[w];
            S_s = sum;
        }
        __syncthreads();

        const float wpre = (tid < AA && scm > -1e8f) ? (ev / S_s) : 0.f;
        t = wpre;
#pragma unroll
        for (int o = 16; o > 0; o >>= 1)
            t += __shfl_xor_sync(0xffffffffu, t, o);
        if (lane == 0) red_s[wid] = t;
        __syncthreads();
        if (tid == 0) {
            float sum = 0.f;
#pragma unroll
            for (int w = 0; w < 8; w++) sum += red_s[w];
            sum2_s = sum;
        }
        __syncthreads();

        if (tid < AA)
            out[rowbase + tid] = wpre / (sum2_s + 1e-8f);
        __syncthreads();   // red_s reuse for next row
    }
}

// ---------------------------------------------------------------------------
extern "C" void kernel_launch(void* const* d_in, const int* in_sizes, int n_in,
                              void* d_out, int out_size)
{
    const float* coord    = (const float*)d_in[0];
    const float* goal     = (const float*)d_in[1];
    const float* frontier = (const float*)d_in[2];
    const float* rel      = (const float*)d_in[3];
    const int*   adj      = (const int*)d_in[4];
    const float* base     = (const float*)d_in[5];
    const float* gc       = (const float*)d_in[6];
    const float* W1       = (const float*)d_in[7];
    const float* b1       = (const float*)d_in[8];
    const float* W2       = (const float*)d_in[9];
    const float* b2       = (const float*)d_in[10];
    float* out = (float*)d_out;

    precompute_kernel<<<392, 128>>>(coord, goal, frontier, gc, W1, b1);
    dim3 grid(AA / 2, BB);
    edge_kernel<<<grid, 256>>>(rel, adj, base, W1, W2, b2, out);
}

// round 8
// speedup vs baseline: 2.0101x; 1.0338x over previous
#include <cuda_runtime.h>
#include <math.h>

// Problem constants
#define BB   8
#define AA   192
#define DD   128
#define RELN 5
#define HH   128
#define EE   (BB*AA*AA)   // 294912 edges
#define KK   384          // K-dim of i/j precompute GEMM (3*D)

// Packed f32x2 helpers (sm_103a FFMA2 path)
#define PACK2(out, lo, hi)  asm("mov.b64 %0, {%1, %2};" : "=l"(out) : "f"(lo), "f"(hi))
#define UNPACK2(lo, hi, in) asm("mov.b64 {%0, %1}, %2;" : "=f"(lo), "=f"(hi) : "l"(in))
#define ADD2(d, a, b)       asm("add.rn.f32x2 %0, %1, %2;" : "=l"(d) : "l"(a), "l"(b))
#define FMA2(d, a, b, c)    asm("fma.rn.f32x2 %0, %1, %2, %3;" : "=l"(d) : "l"(a), "l"(b), "l"(c))

// Scratch (no cudaMalloc allowed)
__device__ float g_pre_i[BB*AA*HH];   // f(i) partial pre-activation
__device__ float g_pre_j[BB*AA*HH];   // f(j) partial pre-activation
__device__ float g_pre_g[BB*HH];      // graph-context partial + b1

// ---------------------------------------------------------------------------
// Kernel 1: precompute pre_i / pre_j  (+ fused pre_g tail blocks).
// 256 threads: col = tid&127, half = tid>>7 owns rows half*4 .. half*4+3.
// W1 chunks double-buffered in smem (coalesced loads); x as xs[d][row].
// ---------------------------------------------------------------------------
#define CH   16            // K-chunk size
#define NCH  (KK/CH)       // 24 chunks
#define XPAD 12            // xs row stride in floats (48B, float4-aligned)

__global__ __launch_bounds__(256) void precompute_kernel(
    const float* __restrict__ coord, const float* __restrict__ goal,
    const float* __restrict__ frontier, const float* __restrict__ gc,
    const float* __restrict__ W1, const float* __restrict__ b1)
{
    __shared__ __align__(16) float xs[KK][XPAD];   // [d][row 0..7]
    __shared__ float ws[2][CH][128];               // staged W1 chunks

    const int tid = threadIdx.x;   // 0..255

    if (blockIdx.x >= 384) {
        // ---- pre_g ----
        const int b = blockIdx.x - 384;
        __shared__ float gs[DD];
        if (tid < DD) gs[tid] = gc[b * DD + tid];
        __syncthreads();
        if (tid < HH) {
            float acc = b1[tid];
#pragma unroll 8
            for (int d = 0; d < DD; d++)
                acc = fmaf(gs[d], W1[(6 * DD + RELN + d) * HH + tid], acc);
            g_pre_g[b * HH + tid] = acc;
        }
        return;
    }

    const int row0  = (blockIdx.x >> 1) * 8;
    const int which = blockIdx.x & 1;
    const int col   = tid & 127;
    const int half  = tid >> 7;

    // Load x rows: coalesced global reads, xs[c][rr] layout
    for (int idx = tid; idx < 8 * KK; idx += 256) {
        const int rr = idx / KK, c = idx % KK;
        const int s = c >> 7, d = c & 127;
        const float* src = (s == 0) ? coord : ((s == 1) ? goal : frontier);
        xs[c][rr] = src[(row0 + rr) * DD + d];
    }

    const int wofs = which * 128;

    float tmp[8];
    // prologue: chunk 0 (each thread stages 8 of the 16x128 chunk)
#pragma unroll
    for (int q = 0; q < 8; q++) {
        const int d = half * 8 + q;
        tmp[q] = W1[((d >> 7) * 256 + wofs + (d & 127)) * HH + col];
    }
#pragma unroll
    for (int q = 0; q < 8; q++) ws[0][half * 8 + q][col] = tmp[q];
    __syncthreads();

    float a0 = 0.f, a1 = 0.f, a2 = 0.f, a3 = 0.f;

    for (int c = 0; c < NCH; c++) {
        const int buf = c & 1;
        if (c + 1 < NCH) {
            const int d0 = (c + 1) * CH;
#pragma unroll
            for (int q = 0; q < 8; q++) {
                const int d = d0 + half * 8 + q;
                tmp[q] = W1[((d >> 7) * 256 + wofs + (d & 127)) * HH + col];
            }
        }
        const int d0 = c * CH;
#pragma unroll
        for (int dd = 0; dd < CH; dd++) {
            const float w = ws[buf][dd][col];
            const float4 x = *(const float4*)&xs[d0 + dd][half * 4];
            a0 = fmaf(w, x.x, a0); a1 = fmaf(w, x.y, a1);
            a2 = fmaf(w, x.z, a2); a3 = fmaf(w, x.w, a3);
        }
        if (c + 1 < NCH) {
#pragma unroll
            for (int q = 0; q < 8; q++) ws[buf ^ 1][half * 8 + q][col] = tmp[q];
        }
        __syncthreads();
    }

    float* dst = which ? g_pre_j : g_pre_i;
    const int r = row0 + half * 4;
    dst[(r + 0) * HH + col] = a0;
    dst[(r + 1) * HH + col] = a1;
    dst[(r + 2) * HH + col] = a2;
    dst[(r + 3) * HH + col] = a3;
}

// ---------------------------------------------------------------------------
// Kernel 2: edge MLP + masked softmax.  One block per (b, i-pair); 8 warps,
// each warp owns one j per iteration (both i-rows from one pre_j load).
// f32x2 packed math; pre_j software-pipelined; fused 4-barrier post phase.
// ---------------------------------------------------------------------------
__global__ __launch_bounds__(256) void edge_kernel(
    const float* __restrict__ rel,        // [B,A,A,5]
    const int* __restrict__ adj,          // [B,A,A] bool as int32
    const float* __restrict__ base,       // [B,A,A]
    const float* __restrict__ W1,
    const float* __restrict__ W2,         // [H,1]
    const float* __restrict__ b2,         // [1]
    float* __restrict__ out)              // [3*E]: weights | score(masked) | learned
{
    const int i0 = blockIdx.x * 2, b = blockIdx.y;
    const int tid  = threadIdx.x;
    const int wid  = tid >> 5, lane = tid & 31;

    __shared__ __align__(16) float rel_s[2][AA][8];  // padded rel rows, 12 KB
    __shared__ float ln_s[2][AA];
    __shared__ float red4[8][4];
    __shared__ float fin[4];

    // stage rel rows for i0, i0+1 into padded smem
    {
        const float* rbase = rel + (long)(b * AA + i0) * AA * RELN;
        float* rdst = &rel_s[0][0][0];
        for (int idx = tid; idx < 2 * AA * RELN; idx += 256) {
            const int e = idx / RELN, m = idx - e * RELN;
            rdst[e * 8 + m] = rbase[idx];
        }
    }

    // register-resident per-channel constants (channels 4*lane .. 4*lane+3), packed
    const float4 pg4 = ((const float4*)&g_pre_g[b * HH])[lane];
    const float4 pi0 = ((const float4*)&g_pre_i[(b * AA + i0) * HH])[lane];
    const float4 pi1 = ((const float4*)&g_pre_i[(b * AA + i0 + 1) * HH])[lane];
    unsigned long long biasp[2][2];
    PACK2(biasp[0][0], pi0.x + pg4.x, pi0.y + pg4.y);
    PACK2(biasp[0][1], pi0.z + pg4.z, pi0.w + pg4.w);
    PACK2(biasp[1][0], pi1.x + pg4.x, pi1.y + pg4.y);
    PACK2(biasp[1][1], pi1.z + pg4.z, pi1.w + pg4.w);
    const float4 w2v = ((const float4*)W2)[lane];
    unsigned long long wrp[RELN][2];
#pragma unroll
    for (int r = 0; r < RELN; r++) {
        const float4 w = ((const float4*)&W1[(6 * DD + r) * HH])[lane];
        PACK2(wrp[r][0], w.x, w.y);
        PACK2(wrp[r][1], w.z, w.w);
    }
    const float b2v = b2[0];

    const ulonglong2* prejv = (const ulonglong2*)g_pre_j;
    __syncthreads();

    // software-pipelined main loop
    ulonglong2 pjc = prejv[(b * AA + wid) * (HH / 4) + lane];
#pragma unroll 2
    for (int j = wid; j < AA; j += 8) {
        const int jn = j + 8;
        ulonglong2 pjn;
        if (jn < AA) pjn = prejv[(b * AA + jn) * (HH / 4) + lane];

        float acc0, acc1;
#pragma unroll
        for (int ii = 0; ii < 2; ii++) {
            const float4 rv = *(const float4*)&rel_s[ii][j][0];
            const float r4s = rel_s[ii][j][4];
            unsigned long long r0p, r1p, r2p, r3p, r4p;
            PACK2(r0p, rv.x, rv.x); PACK2(r1p, rv.y, rv.y);
            PACK2(r2p, rv.z, rv.z); PACK2(r3p, rv.w, rv.w);
            PACK2(r4p, r4s, r4s);

            unsigned long long h01, h23;
            ADD2(h01, biasp[ii][0], pjc.x);
            ADD2(h23, biasp[ii][1], pjc.y);
            FMA2(h01, r0p, wrp[0][0], h01); FMA2(h23, r0p, wrp[0][1], h23);
            FMA2(h01, r1p, wrp[1][0], h01); FMA2(h23, r1p, wrp[1][1], h23);
            FMA2(h01, r2p, wrp[2][0], h01); FMA2(h23, r2p, wrp[2][1], h23);
            FMA2(h01, r3p, wrp[3][0], h01); FMA2(h23, r3p, wrp[3][1], h23);
            FMA2(h01, r4p, wrp[4][0], h01); FMA2(h23, r4p, wrp[4][1], h23);

            float hx, hy, hz, hw;
            UNPACK2(hx, hy, h01);
            UNPACK2(hz, hw, h23);
            hx = fmaxf(hx, 0.f); hy = fmaxf(hy, 0.f);
            hz = fmaxf(hz, 0.f); hw = fmaxf(hw, 0.f);
            float acc = hx * w2v.x;
            acc = fmaf(hy, w2v.y, acc);
            acc = fmaf(hz, w2v.z, acc);
            acc = fmaf(hw, w2v.w, acc);
            if (ii) acc1 = acc; else acc0 = acc;
        }
#pragma unroll
        for (int o = 16; o > 0; o >>= 1) {
            acc0 += __shfl_xor_sync(0xffffffffu, acc0, o);
            acc1 += __shfl_xor_sync(0xffffffffu, acc1, o);
        }
        if (lane == 0) {
            ln_s[0][j] = acc0 + b2v;
            ln_s[1][j] = acc1 + b2v;
        }
        pjc = pjn;
    }
    __syncthreads();

    // ---- fused post phase: both rows at once, 4 barriers total ----
    const int r0base = (b * AA + i0) * AA;
    const int r1base = r0base + AA;

    float lv0 = 0.f, lv1 = 0.f, sc0 = -INFINITY, sc1 = -INFINITY;
    int a0f = 0, a1f = 0;
    if (tid < AA) {
        lv0 = ln_s[0][tid]; lv1 = ln_s[1][tid];
        a0f = adj[r0base + tid]; a1f = adj[r1base + tid];
        sc0 = a0f ? base[r0base + tid] + lv0 : -1e9f;
        sc1 = a1f ? base[r1base + tid] + lv1 : -1e9f;
        out[EE   + r0base + tid] = sc0;   // score (masked, as reference returns)
        out[2*EE + r0base + tid] = lv0;   // learned (unmasked)
        out[EE   + r1base + tid] = sc1;
        out[2*EE + r1base + tid] = lv1;
    }

    float m0 = sc0, m1 = sc1;
#pragma unroll
    for (int o = 16; o > 0; o >>= 1) {
        m0 = fmaxf(m0, __shfl_xor_sync(0xffffffffu, m0, o));
        m1 = fmaxf(m1, __shfl_xor_sync(0xffffffffu, m1, o));
    }
    if (lane == 0) { red4[wid][0] = m0; red4[wid][1] = m1; }
    __syncthreads();
    if (tid == 0) {
        float x0 = red4[0][0], x1 = red4[0][1];
#pragma unroll
        for (int w = 1; w < 8; w++) {
            x0 = fmaxf(x0, red4[w][0]);
            x1 = fmaxf(x1, red4[w][1]);
        }
        fin[0] = x0; fin[1] = x1;
    }
    __syncthreads();
    const float mx0 = fin[0], mx1 = fin[1];

    // ev: masked (-1e9) underflows to exactly 0; all-masked row -> ev=1, t=0
    const float ev0 = (tid < AA) ? __expf(sc0 - mx0) : 0.f;
    const float ev1 = (tid < AA) ? __expf(sc1 - mx1) : 0.f;
    float t0 = a0f ? ev0 : 0.f;
    float t1 = a1f ? ev1 : 0.f;

    float S0 = ev0, S1 = ev1, T0 = t0, T1 = t1;
#pragma unroll
    for (int o = 16; o > 0; o >>= 1) {
        S0 += __shfl_xor_sync(0xffffffffu, S0, o);
        T0 += __shfl_xor_sync(0xffffffffu, T0, o);
        S1 += __shfl_xor_sync(0xffffffffu, S1, o);
        T1 += __shfl_xor_sync(0xffffffffu, T1, o);
    }
    if (lane == 0) {
        red4[wid][0] = S0; red4[wid][1] = T0;
        red4[wid][2] = S1; red4[wid][3] = T1;
    }
    __syncthreads();
    if (tid == 0) {
        float s0 = 0.f, tt0 = 0.f, s1 = 0.f, tt1 = 0.f;
#pragma unroll
        for (int w = 0; w < 8; w++) {
            s0 += red4[w][0]; tt0 += red4[w][1];
            s1 += red4[w][2]; tt1 += red4[w][3];
        }
        // weight = adj*ev / (T + 1e-8*S)  ==  (ev/S)*adj / (T/S + 1e-8)
        fin[0] = 1.f / (tt0 + 1e-8f * s0);
        fin[1] = 1.f / (tt1 + 1e-8f * s1);
    }
    __syncthreads();

    if (tid < AA) {
        out[r0base + tid] = t0 * fin[0];
        out[r1base + tid] = t1 * fin[1];
    }
}

// ---------------------------------------------------------------------------
extern "C" void kernel_launch(void* const* d_in, const int* in_sizes, int n_in,
                              void* d_out, int out_size)
{
    const float* coord    = (const float*)d_in[0];
    const float* goal     = (const float*)d_in[1];
    const float* frontier = (const float*)d_in[2];
    const float* rel      = (const float*)d_in[3];
    const int*   adj      = (const int*)d_in[4];
    const float* base     = (const float*)d_in[5];
    const float* gc       = (const float*)d_in[6];
    const float* W1       = (const float*)d_in[7];
    const float* b1       = (const float*)d_in[8];
    const float* W2       = (const float*)d_in[9];
    const float* b2       = (const float*)d_in[10];
    float* out = (float*)d_out;

    precompute_kernel<<<392, 256>>>(coord, goal, frontier, gc, W1, b1);
    dim3 grid(AA / 2, BB);
    edge_kernel<<<grid, 256>>>(rel, adj, base, W1, W2, b2, out);
}

// round 11
// speedup vs baseline: 2.2682x; 1.1284x over previous
#include <cuda_runtime.h>
#include <math.h>

// Problem constants
#define BB   8
#define AA   192
#define DD   128
#define RELN 5
#define HH   128
#define EE   (BB*AA*AA)   // 294912 edges
#define KK   384          // K-dim of i/j precompute GEMM (3*D)

// Packed f32x2 helpers (sm_103a FFMA2 path)
#define PACK2(out, lo, hi)  asm("mov.b64 %0, {%1, %2};" : "=l"(out) : "f"(lo), "f"(hi))
#define UNPACK2(lo, hi, in) asm("mov.b64 {%0, %1}, %2;" : "=f"(lo), "=f"(hi) : "l"(in))
#define ADD2(d, a, b)       asm("add.rn.f32x2 %0, %1, %2;" : "=l"(d) : "l"(a), "l"(b))
#define FMA2(d, a, b, c)    asm("fma.rn.f32x2 %0, %1, %2, %3;" : "=l"(d) : "l"(a), "l"(b), "l"(c))

// Scratch (no cudaMalloc allowed)
__device__ float g_pre_i[BB*AA*HH];                 // f(i) partial, row-major [b][i][k]
__device__ __align__(16) float g_pre_jT[BB*AA*HH];  // f(j) transposed-packed [b][k/4][j][4]
__device__ float g_pre_g[BB*HH];                    // graph-context partial + b1

// ---------------------------------------------------------------------------
// Kernel 1: precompute pre_i / pre_jT  (+ fused pre_g tail blocks).
// 128 threads (R6-measured config): col = tid, 8 rows per block.
// which=0 -> pre_i row-major; which=1 -> pre_jT transposed-packed.
// ---------------------------------------------------------------------------
#define CH   16            // K-chunk size
#define NCH  (KK/CH)       // 24 chunks
#define XPAD 12            // xs row stride in floats

__global__ __launch_bounds__(128) void precompute_kernel(
    const float* __restrict__ coord, const float* __restrict__ goal,
    const float* __restrict__ frontier, const float* __restrict__ gc,
    const float* __restrict__ W1, const float* __restrict__ b1)
{
    __shared__ __align__(16) float xs[KK][XPAD];   // [d][row 0..7]
    __shared__ float ws[2][CH][128];               // staged W1 chunks

    const int tid = threadIdx.x;   // 0..127 == output col k

    if (blockIdx.x >= 384) {
        // ---- pre_g ----
        const int b = blockIdx.x - 384;
        float* gs = &xs[0][0];
        gs[tid] = gc[b * DD + tid];
        __syncthreads();
        float acc = b1[tid];
#pragma unroll 8
        for (int d = 0; d < DD; d++)
            acc = fmaf(gs[d], W1[(6 * DD + RELN + d) * HH + tid], acc);
        g_pre_g[b * HH + tid] = acc;
        return;
    }

    const int row0  = (blockIdx.x >> 1) * 8;
    const int which = blockIdx.x & 1;

    // Load x rows: coalesced global reads, xs[c][rr] smem layout
    for (int idx = tid; idx < 8 * KK; idx += 128) {
        const int rr = idx / KK, c = idx % KK;
        const int s = c >> 7, d = c & 127;
        const float* src = (s == 0) ? coord : ((s == 1) ? goal : frontier);
        xs[c][rr] = src[(row0 + rr) * DD + d];
    }

    const int wofs = which * 128;

    float tmp[CH];
#pragma unroll
    for (int dd = 0; dd < CH; dd++)
        tmp[dd] = W1[((dd >> 7) * 256 + wofs + (dd & 127)) * HH + tid];
#pragma unroll
    for (int dd = 0; dd < CH; dd++) ws[0][dd][tid] = tmp[dd];
    __syncthreads();

    float a0 = 0.f, a1 = 0.f, a2 = 0.f, a3 = 0.f;
    float a4 = 0.f, a5 = 0.f, a6 = 0.f, a7 = 0.f;

    for (int c = 0; c < NCH; c++) {
        const int buf = c & 1;
        if (c + 1 < NCH) {
            const int d0 = (c + 1) * CH;
#pragma unroll
            for (int dd = 0; dd < CH; dd++) {
                const int d = d0 + dd;
                tmp[dd] = W1[((d >> 7) * 256 + wofs + (d & 127)) * HH + tid];
            }
        }
        const int d0 = c * CH;
#pragma unroll
        for (int dd = 0; dd < CH; dd++) {
            const float w = ws[buf][dd][tid];
            const float4 xlo = *(const float4*)&xs[d0 + dd][0];
            const float4 xhi = *(const float4*)&xs[d0 + dd][4];
            a0 = fmaf(w, xlo.x, a0); a1 = fmaf(w, xlo.y, a1);
            a2 = fmaf(w, xlo.z, a2); a3 = fmaf(w, xlo.w, a3);
            a4 = fmaf(w, xhi.x, a4); a5 = fmaf(w, xhi.y, a5);
            a6 = fmaf(w, xhi.z, a6); a7 = fmaf(w, xhi.w, a7);
        }
        if (c + 1 < NCH) {
#pragma unroll
            for (int dd = 0; dd < CH; dd++) ws[buf ^ 1][dd][tid] = tmp[dd];
        }
        __syncthreads();
    }

    if (which == 0) {
        float* dst = g_pre_i;
        dst[(row0 + 0) * HH + tid] = a0;
        dst[(row0 + 1) * HH + tid] = a1;
        dst[(row0 + 2) * HH + tid] = a2;
        dst[(row0 + 3) * HH + tid] = a3;
        dst[(row0 + 4) * HH + tid] = a4;
        dst[(row0 + 5) * HH + tid] = a5;
        dst[(row0 + 6) * HH + tid] = a6;
        dst[(row0 + 7) * HH + tid] = a7;
    } else {
        // transposed-packed: g_pre_jT[((b*32 + k/4)*AA + j)*4 + k%4]
        const int b  = row0 / AA;
        const int j0 = row0 % AA;
        const int kq = tid >> 2, kr = tid & 3;
        const long bofs = ((long)(b * 32 + kq) * AA + j0) * 4 + kr;
        float av[8] = {a0, a1, a2, a3, a4, a5, a6, a7};
#pragma unroll
        for (int rr = 0; rr < 8; rr++)
            g_pre_jT[bofs + rr * 4] = av[rr];
    }
}

// ---------------------------------------------------------------------------
// Kernel 2: edge MLP + masked softmax.  One block per (b, 4 i-rows).
// 192 threads, 6 warps; lane owns one j (j = wid*32 + lane), accumulates
// learned(i,j) over channels k with per-lane accs -> NO warp reductions in
// the mainloop.  Channel constants pre-packed in smem cst[]; pre_jT read as
// coalesced LDG.128 (4 channels per load), software-pipelined.
// ---------------------------------------------------------------------------
__global__ __launch_bounds__(192) void edge_kernel(
    const float* __restrict__ rel,        // [B,A,A,5]
    const int* __restrict__ adj,          // [B,A,A] bool as int32
    const float* __restrict__ base,       // [B,A,A]
    const float* __restrict__ W1,
    const float* __restrict__ W2,         // [H,1]
    const float* __restrict__ b2,         // [1]
    float* __restrict__ out)              // [3*E]: weights | score(masked) | learned
{
    const int i0 = blockIdx.x * 4, b = blockIdx.y;
    const int tid  = threadIdx.x;         // 0..191
    const int wid  = tid >> 5, lane = tid & 31;
    const int j    = tid;                 // also: j = wid*32+lane

    __shared__ __align__(16) unsigned long long cst[HH * 8];
    // cst[k*8 + 0] = {bias_i0, bias_i1}   (pre_i + pre_g)
    // cst[k*8 + 1] = {bias_i2, bias_i3}
    // cst[k*8 + 2..6] = {w1r[r][k], w1r[r][k]}  r = 0..4
    // cst[k*8 + 7] = {w2[k], w2[k]}
    __shared__ float ln_s[4][AA];
    __shared__ float red_s[6][8];
    __shared__ float fin[4];

    // ---- build cst (threads 0..127) ----
    if (tid < HH) {
        const int k = tid;
        const float pg = g_pre_g[b * HH + k];
        const float p0 = g_pre_i[(b * AA + i0 + 0) * HH + k] + pg;
        const float p1 = g_pre_i[(b * AA + i0 + 1) * HH + k] + pg;
        const float p2 = g_pre_i[(b * AA + i0 + 2) * HH + k] + pg;
        const float p3 = g_pre_i[(b * AA + i0 + 3) * HH + k] + pg;
        unsigned long long t;
        PACK2(t, p0, p1); cst[k * 8 + 0] = t;
        PACK2(t, p2, p3); cst[k * 8 + 1] = t;
#pragma unroll
        for (int r = 0; r < RELN; r++) {
            const float w = W1[(6 * DD + r) * HH + k];
            PACK2(t, w, w); cst[k * 8 + 2 + r] = t;
        }
        const float w2k = W2[k];
        PACK2(t, w2k, w2k); cst[k * 8 + 7] = t;
    }

    // ---- rel(i0..i0+3, j) into packed registers ----
    const float* rb = rel + ((long)(b * AA + i0) * AA + j) * RELN;
    unsigned long long rp01[RELN], rp23[RELN];
#pragma unroll
    for (int r = 0; r < RELN; r++) {
        PACK2(rp01[r], rb[r],                rb[AA * RELN + r]);
        PACK2(rp23[r], rb[2 * AA * RELN + r], rb[3 * AA * RELN + r]);
    }
    const float b2v = b2[0];
    __syncthreads();

    // ---- mainloop over channels ----
    const float4* pjt = (const float4*)g_pre_jT + (long)(b * 32) * AA + j;
    float acc0 = 0.f, acc1 = 0.f, acc2 = 0.f, acc3 = 0.f;
    float4 cur = pjt[0];
#pragma unroll 2
    for (int kq = 0; kq < 32; kq++) {
        float4 nxt;
        if (kq < 31) nxt = pjt[(kq + 1) * AA];
#pragma unroll
        for (int q = 0; q < 4; q++) {
            const int k = kq * 4 + q;
            const ulonglong2* c = (const ulonglong2*)&cst[k * 8];
            const ulonglong2 cb   = c[0];
            const ulonglong2 cw01 = c[1];
            const ulonglong2 cw23 = c[2];
            const ulonglong2 cw4v = c[3];
            const float pj = (&cur.x)[q];
            unsigned long long pjp;
            PACK2(pjp, pj, pj);
            unsigned long long h01, h23;
            ADD2(h01, cb.x, pjp);
            ADD2(h23, cb.y, pjp);
            FMA2(h01, rp01[0], cw01.x, h01); FMA2(h23, rp23[0], cw01.x, h23);
            FMA2(h01, rp01[1], cw01.y, h01); FMA2(h23, rp23[1], cw01.y, h23);
            FMA2(h01, rp01[2], cw23.x, h01); FMA2(h23, rp23[2], cw23.x, h23);
            FMA2(h01, rp01[3], cw23.y, h01); FMA2(h23, rp23[3], cw23.y, h23);
            FMA2(h01, rp01[4], cw4v.x, h01); FMA2(h23, rp23[4], cw4v.x, h23);
            float h0, h1, h2, h3, w2k, w2d;
            UNPACK2(h0, h1, h01);
            UNPACK2(h2, h3, h23);
            UNPACK2(w2k, w2d, cw4v.y);
            h0 = fmaxf(h0, 0.f); h1 = fmaxf(h1, 0.f);
            h2 = fmaxf(h2, 0.f); h3 = fmaxf(h3, 0.f);
            acc0 = fmaf(h0, w2k, acc0);
            acc1 = fmaf(h1, w2k, acc1);
            acc2 = fmaf(h2, w2k, acc2);
            acc3 = fmaf(h3, w2k, acc3);
        }
        cur = nxt;
    }

    ln_s[0][j] = acc0 + b2v;
    ln_s[1][j] = acc1 + b2v;
    ln_s[2][j] = acc2 + b2v;
    ln_s[3][j] = acc3 + b2v;
    __syncthreads();

    // ---- post phase: 4 rows fused (every thread owns j = tid < 192) ----
    float lv[4], sc[4], tmv[4];
    int   af[4], rbs[4];
#pragma unroll
    for (int ii = 0; ii < 4; ii++) {
        const int rbase = (b * AA + i0 + ii) * AA + j;
        rbs[ii] = rbase;
        lv[ii]  = ln_s[ii][j];
        af[ii]  = adj[rbase];
        sc[ii]  = af[ii] ? base[rbase] + lv[ii] : -1e9f;
        out[EE   + rbase] = sc[ii];   // score (masked, as reference returns)
        out[2*EE + rbase] = lv[ii];   // learned (unmasked)
    }

    float m[4] = {sc[0], sc[1], sc[2], sc[3]};
#pragma unroll
    for (int o = 16; o > 0; o >>= 1) {
#pragma unroll
        for (int ii = 0; ii < 4; ii++)
            m[ii] = fmaxf(m[ii], __shfl_xor_sync(0xffffffffu, m[ii], o));
    }
    if (lane == 0) {
#pragma unroll
        for (int ii = 0; ii < 4; ii++) red_s[wid][ii] = m[ii];
    }
    __syncthreads();
    if (tid < 4) {
        float x = red_s[0][tid];
#pragma unroll
        for (int w = 1; w < 6; w++) x = fmaxf(x, red_s[w][tid]);
        fin[tid] = x;
    }
    __syncthreads();

    float S[4], T[4];
#pragma unroll
    for (int ii = 0; ii < 4; ii++) {
        const float ev = __expf(sc[ii] - fin[ii]);  // masked -> exact 0 (or 1 if all-masked)
        tmv[ii] = af[ii] ? ev : 0.f;
        S[ii] = ev; T[ii] = tmv[ii];
    }
#pragma unroll
    for (int o = 16; o > 0; o >>= 1) {
#pragma unroll
        for (int ii = 0; ii < 4; ii++) {
            S[ii] += __shfl_xor_sync(0xffffffffu, S[ii], o);
            T[ii] += __shfl_xor_sync(0xffffffffu, T[ii], o);
        }
    }
    if (lane == 0) {
#pragma unroll
        for (int ii = 0; ii < 4; ii++) {
            red_s[wid][ii]     = S[ii];
            red_s[wid][4 + ii] = T[ii];
        }
    }
    __syncthreads();
    if (tid < 4) {
        float s = 0.f, t = 0.f;
#pragma unroll
        for (int w = 0; w < 6; w++) { s += red_s[w][tid]; t += red_s[w][4 + tid]; }
        // weight = adj*ev / (T + 1e-8*S)   (== reference (ev/S)*adj / (T/S + 1e-8))
        fin[tid] = 1.f / (t + 1e-8f * s);
    }
    __syncthreads();

#pragma unroll
    for (int ii = 0; ii < 4; ii++)
        out[rbs[ii]] = tmv[ii] * fin[ii];
}

// ---------------------------------------------------------------------------
extern "C" void kernel_launch(void* const* d_in, const int* in_sizes, int n_in,
                              void* d_out, int out_size)
{
    const float* coord    = (const float*)d_in[0];
    const float* goal     = (const float*)d_in[1];
    const float* frontier = (const float*)d_in[2];
    const float* rel      = (const float*)d_in[3];
    const int*   adj      = (const int*)d_in[4];
    const float* base     = (const float*)d_in[5];
    const float* gc       = (const float*)d_in[6];
    const float* W1       = (const float*)d_in[7];
    const float* b1       = (const float*)d_in[8];
    const float* W2       = (const float*)d_in[9];
    const float* b2       = (const float*)d_in[10];
    float* out = (float*)d_out;

    precompute_kernel<<<392, 128>>>(coord, goal, frontier, gc, W1, b1);
    dim3 grid(AA / 4, BB);
    edge_kernel<<<grid, 192>>>(rel, adj, base, W1, W2, b2, out);
}

// round 12
// speedup vs baseline: 2.2789x; 1.0047x over previous
#include <cuda_runtime.h>
#include <math.h>

// Problem constants
#define BB   8
#define AA   192
#define DD   128
#define RELN 5
#define HH   128
#define EE   (BB*AA*AA)   // 294912 edges
#define KK   384          // K-dim of i/j precompute GEMM (3*D)

// Packed f32x2 helpers (sm_103a FFMA2 path)
#define PACK2(out, lo, hi)  asm("mov.b64 %0, {%1, %2};" : "=l"(out) : "f"(lo), "f"(hi))
#define UNPACK2(lo, hi, in) asm("mov.b64 {%0, %1}, %2;" : "=f"(lo), "=f"(hi) : "l"(in))
#define ADD2(d, a, b)       asm("add.rn.f32x2 %0, %1, %2;" : "=l"(d) : "l"(a), "l"(b))
#define FMA2(d, a, b, c)    asm("fma.rn.f32x2 %0, %1, %2, %3;" : "=l"(d) : "l"(a), "l"(b), "l"(c))

// Scratch (no cudaMalloc allowed)
__device__ float g_pre_i[BB*AA*HH];                 // f(i) partial, row-major [b][i][k]
__device__ __align__(16) float g_pre_jT[BB*AA*HH];  // f(j) transposed-packed [b][k/4][j][4]
__device__ float g_pre_g[BB*HH];                    // graph-context partial + b1

// ---------------------------------------------------------------------------
// Kernel 1: precompute pre_i / pre_jT  (+ fused pre_g tail blocks).
// 128 threads: col = tid, 8 rows per block.
// which=0 -> pre_i row-major (coalesced); which=1 -> pre_jT via smem
// transpose so every warp-store is one contiguous 128B segment.
// ---------------------------------------------------------------------------
#define CH   16            // K-chunk size
#define NCH  (KK/CH)       // 24 chunks
#define XPAD 12            // xs row stride in floats

__global__ __launch_bounds__(128) void precompute_kernel(
    const float* __restrict__ coord, const float* __restrict__ goal,
    const float* __restrict__ frontier, const float* __restrict__ gc,
    const float* __restrict__ W1, const float* __restrict__ b1)
{
    __shared__ __align__(16) float xs[KK][XPAD];   // [d][row 0..7]
    __shared__ float ws[2][CH][128];               // staged W1 chunks
    __shared__ float ts[HH * 9];                   // transpose staging (pad 9)

    const int tid = threadIdx.x;   // 0..127 == output col k

    if (blockIdx.x >= 384) {
        // ---- pre_g ----
        const int b = blockIdx.x - 384;
        float* gs = &xs[0][0];
        gs[tid] = gc[b * DD + tid];
        __syncthreads();
        float acc = b1[tid];
#pragma unroll 8
        for (int d = 0; d < DD; d++)
            acc = fmaf(gs[d], W1[(6 * DD + RELN + d) * HH + tid], acc);
        g_pre_g[b * HH + tid] = acc;
        return;
    }

    const int row0  = (blockIdx.x >> 1) * 8;
    const int which = blockIdx.x & 1;

    // Load x rows: coalesced global reads, xs[c][rr] smem layout
    for (int idx = tid; idx < 8 * KK; idx += 128) {
        const int rr = idx / KK, c = idx % KK;
        const int s = c >> 7, d = c & 127;
        const float* src = (s == 0) ? coord : ((s == 1) ? goal : frontier);
        xs[c][rr] = src[(row0 + rr) * DD + d];
    }

    const int wofs = which * 128;

    float tmp[CH];
#pragma unroll
    for (int dd = 0; dd < CH; dd++)
        tmp[dd] = W1[((dd >> 7) * 256 + wofs + (dd & 127)) * HH + tid];
#pragma unroll
    for (int dd = 0; dd < CH; dd++) ws[0][dd][tid] = tmp[dd];
    __syncthreads();

    float a0 = 0.f, a1 = 0.f, a2 = 0.f, a3 = 0.f;
    float a4 = 0.f, a5 = 0.f, a6 = 0.f, a7 = 0.f;

    for (int c = 0; c < NCH; c++) {
        const int buf = c & 1;
        if (c + 1 < NCH) {
            const int d0 = (c + 1) * CH;
#pragma unroll
            for (int dd = 0; dd < CH; dd++) {
                const int d = d0 + dd;
                tmp[dd] = W1[((d >> 7) * 256 + wofs + (d & 127)) * HH + tid];
            }
        }
        const int d0 = c * CH;
#pragma unroll
        for (int dd = 0; dd < CH; dd++) {
            const float w = ws[buf][dd][tid];
            const float4 xlo = *(const float4*)&xs[d0 + dd][0];
            const float4 xhi = *(const float4*)&xs[d0 + dd][4];
            a0 = fmaf(w, xlo.x, a0); a1 = fmaf(w, xlo.y, a1);
            a2 = fmaf(w, xlo.z, a2); a3 = fmaf(w, xlo.w, a3);
            a4 = fmaf(w, xhi.x, a4); a5 = fmaf(w, xhi.y, a5);
            a6 = fmaf(w, xhi.z, a6); a7 = fmaf(w, xhi.w, a7);
        }
        if (c + 1 < NCH) {
#pragma unroll
            for (int dd = 0; dd < CH; dd++) ws[buf ^ 1][dd][tid] = tmp[dd];
        }
        __syncthreads();
    }

    if (which == 0) {
        float* dst = g_pre_i;
        dst[(row0 + 0) * HH + tid] = a0;
        dst[(row0 + 1) * HH + tid] = a1;
        dst[(row0 + 2) * HH + tid] = a2;
        dst[(row0 + 3) * HH + tid] = a3;
        dst[(row0 + 4) * HH + tid] = a4;
        dst[(row0 + 5) * HH + tid] = a5;
        dst[(row0 + 6) * HH + tid] = a6;
        dst[(row0 + 7) * HH + tid] = a7;
    } else {
        // smem transpose, then coalesced 128B warp-stores to g_pre_jT
        const float av[8] = {a0, a1, a2, a3, a4, a5, a6, a7};
#pragma unroll
        for (int rr = 0; rr < 8; rr++)
            ts[tid * 9 + rr] = av[rr];       // stride 9 -> conflict-free
        __syncthreads();

        const int b  = row0 / AA;
        const int j0 = row0 % AA;
        const int wid  = tid >> 5, lane = tid & 31;
        const int kr = lane & 3, jj = lane >> 2;   // lane = jj*4 + kr
#pragma unroll
        for (int kq = wid; kq < 32; kq += 4) {
            const float v = ts[(kq * 4 + kr) * 9 + jj];
            g_pre_jT[((long)(b * 32 + kq) * AA + j0 + jj) * 4 + kr] = v;
        }
    }
}

// ---------------------------------------------------------------------------
// Kernel 2: edge MLP + masked softmax.  One block per (b, 4 i-rows).
// 384 threads = 2 channel-halves x 192 j-threads (split-K):
//   half = tid/192 owns channels [half*64, half*64+64) for j = tid%192.
// Per-lane accumulators (NO warp reductions in mainloop); partials summed
// through smem.  Channel constants pre-packed in smem cst[]; pre_jT read as
// coalesced LDG.128 (4 channels per load), software-pipelined.
// ---------------------------------------------------------------------------
__global__ __launch_bounds__(384) void edge_kernel(
    const float* __restrict__ rel,        // [B,A,A,5]
    const int* __restrict__ adj,          // [B,A,A] bool as int32
    const float* __restrict__ base,       // [B,A,A]
    const float* __restrict__ W1,
    const float* __restrict__ W2,         // [H,1]
    const float* __restrict__ b2,         // [1]
    float* __restrict__ out)              // [3*E]: weights | score(masked) | learned
{
    const int i0 = blockIdx.x * 4, b = blockIdx.y;
    const int tid  = threadIdx.x;         // 0..383
    const int wid  = tid >> 5, lane = tid & 31;
    const int half = (tid >= 192);        // warps 0..5 -> half 0, 6..11 -> half 1
    const int j    = tid - half * 192;    // 0..191

    __shared__ __align__(16) unsigned long long cst[HH * 8];
    // cst[k*8+0] = {bias_i0, bias_i1}; cst[k*8+1] = {bias_i2, bias_i3}
    // cst[k*8+2..6] = {w1r[r][k], w1r[r][k]}; cst[k*8+7] = {w2[k], w2[k]}
    __shared__ float lnp[2][4][AA];       // per-half partial learned sums
    __shared__ float red_s[6][8];
    __shared__ float fin[4];

    // ---- build cst (threads 0..127) ----
    if (tid < HH) {
        const int k = tid;
        const float pg = g_pre_g[b * HH + k];
        const float p0 = g_pre_i[(b * AA + i0 + 0) * HH + k] + pg;
        const float p1 = g_pre_i[(b * AA + i0 + 1) * HH + k] + pg;
        const float p2 = g_pre_i[(b * AA + i0 + 2) * HH + k] + pg;
        const float p3 = g_pre_i[(b * AA + i0 + 3) * HH + k] + pg;
        unsigned long long t;
        PACK2(t, p0, p1); cst[k * 8 + 0] = t;
        PACK2(t, p2, p3); cst[k * 8 + 1] = t;
#pragma unroll
        for (int r = 0; r < RELN; r++) {
            const float w = W1[(6 * DD + r) * HH + k];
            PACK2(t, w, w); cst[k * 8 + 2 + r] = t;
        }
        const float w2k = W2[k];
        PACK2(t, w2k, w2k); cst[k * 8 + 7] = t;
    }

    // ---- rel(i0..i0+3, j) into packed registers ----
    const float* rb = rel + ((long)(b * AA + i0) * AA + j) * RELN;
    unsigned long long rp01[RELN], rp23[RELN];
#pragma unroll
    for (int r = 0; r < RELN; r++) {
        PACK2(rp01[r], rb[r],                 rb[AA * RELN + r]);
        PACK2(rp23[r], rb[2 * AA * RELN + r], rb[3 * AA * RELN + r]);
    }
    const float b2v = b2[0];
    __syncthreads();

    // ---- mainloop over this half's 64 channels (16 float4 groups) ----
    const float4* pjt = (const float4*)g_pre_jT + (long)(b * 32 + half * 16) * AA + j;
    float acc0 = 0.f, acc1 = 0.f, acc2 = 0.f, acc3 = 0.f;
    float4 cur = pjt[0];
#pragma unroll 2
    for (int kq = 0; kq < 16; kq++) {
        float4 nxt;
        if (kq < 15) nxt = pjt[(kq + 1) * AA];
#pragma unroll
        for (int q = 0; q < 4; q++) {
            const int k = (half * 16 + kq) * 4 + q;
            const ulonglong2* c = (const ulonglong2*)&cst[k * 8];
            const ulonglong2 cb   = c[0];
            const ulonglong2 cw01 = c[1];
            const ulonglong2 cw23 = c[2];
            const ulonglong2 cw4v = c[3];
            const float pj = (&cur.x)[q];
            unsigned long long pjp;
            PACK2(pjp, pj, pj);
            unsigned long long h01, h23;
            ADD2(h01, cb.x, pjp);
            ADD2(h23, cb.y, pjp);
            FMA2(h01, rp01[0], cw01.x, h01); FMA2(h23, rp23[0], cw01.x, h23);
            FMA2(h01, rp01[1], cw01.y, h01); FMA2(h23, rp23[1], cw01.y, h23);
            FMA2(h01, rp01[2], cw23.x, h01); FMA2(h23, rp23[2], cw23.x, h23);
            FMA2(h01, rp01[3], cw23.y, h01); FMA2(h23, rp23[3], cw23.y, h23);
            FMA2(h01, rp01[4], cw4v.x, h01); FMA2(h23, rp23[4], cw4v.x, h23);
            float h0, h1, h2, h3, w2k, w2d;
            UNPACK2(h0, h1, h01);
            UNPACK2(h2, h3, h23);
            UNPACK2(w2k, w2d, cw4v.y);
            h0 = fmaxf(h0, 0.f); h1 = fmaxf(h1, 0.f);
            h2 = fmaxf(h2, 0.f); h3 = fmaxf(h3, 0.f);
            acc0 = fmaf(h0, w2k, acc0);
            acc1 = fmaf(h1, w2k, acc1);
            acc2 = fmaf(h2, w2k, acc2);
            acc3 = fmaf(h3, w2k, acc3);
        }
        cur = nxt;
    }

    lnp[half][0][j] = acc0;
    lnp[half][1][j] = acc1;
    lnp[half][2][j] = acc2;
    lnp[half][3][j] = acc3;
    __syncthreads();

    // ---- post phase: threads 0..191 own j; warps 6..11 ride the barriers ----
    const bool act = (tid < AA);
    float sc[4], tmv[4];
    int   af[4], rbs[4];
#pragma unroll
    for (int ii = 0; ii < 4; ii++) { sc[ii] = -1e30f; tmv[ii] = 0.f; af[ii] = 0; rbs[ii] = 0; }
    if (act) {
#pragma unroll
        for (int ii = 0; ii < 4; ii++) {
            const int rbase = (b * AA + i0 + ii) * AA + tid;
            rbs[ii] = rbase;
            const float lv = lnp[0][ii][tid] + lnp[1][ii][tid] + b2v;
            af[ii]  = adj[rbase];
            sc[ii]  = af[ii] ? base[rbase] + lv : -1e9f;
            out[EE   + rbase] = sc[ii];   // score (masked, as reference returns)
            out[2*EE + rbase] = lv;       // learned (unmasked)
        }
    }

    float m[4] = {sc[0], sc[1], sc[2], sc[3]};
#pragma unroll
    for (int o = 16; o > 0; o >>= 1) {
#pragma unroll
        for (int ii = 0; ii < 4; ii++)
            m[ii] = fmaxf(m[ii], __shfl_xor_sync(0xffffffffu, m[ii], o));
    }
    if (wid < 6 && lane == 0) {
#pragma unroll
        for (int ii = 0; ii < 4; ii++) red_s[wid][ii] = m[ii];
    }
    __syncthreads();
    if (tid < 4) {
        float x = red_s[0][tid];
#pragma unroll
        for (int w = 1; w < 6; w++) x = fmaxf(x, red_s[w][tid]);
        fin[tid] = x;
    }
    __syncthreads();

    float S[4], T[4];
#pragma unroll
    for (int ii = 0; ii < 4; ii++) {
        const float ev = act ? __expf(sc[ii] - fin[ii]) : 0.f;  // masked -> exact 0
        tmv[ii] = af[ii] ? ev : 0.f;
        S[ii] = ev; T[ii] = tmv[ii];
    }
#pragma unroll
    for (int o = 16; o > 0; o >>= 1) {
#pragma unroll
        for (int ii = 0; ii < 4; ii++) {
            S[ii] += __shfl_xor_sync(0xffffffffu, S[ii], o);
            T[ii] += __shfl_xor_sync(0xffffffffu, T[ii], o);
        }
    }
    if (wid < 6 && lane == 0) {
#pragma unroll
        for (int ii = 0; ii < 4; ii++) {
            red_s[wid][ii]     = S[ii];
            red_s[wid][4 + ii] = T[ii];
        }
    }
    __syncthreads();
    if (tid < 4) {
        float s = 0.f, t = 0.f;
#pragma unroll
        for (int w = 0; w < 6; w++) { s += red_s[w][tid]; t += red_s[w][4 + tid]; }
        // weight = adj*ev / (T + 1e-8*S)   (== reference (ev/S)*adj / (T/S + 1e-8))
        fin[tid] = 1.f / (t + 1e-8f * s);
    }
    __syncthreads();

    if (act) {
#pragma unroll
        for (int ii = 0; ii < 4; ii++)
            out[rbs[ii]] = tmv[ii] * fin[ii];
    }
}

// ---------------------------------------------------------------------------
extern "C" void kernel_launch(void* const* d_in, const int* in_sizes, int n_in,
                              void* d_out, int out_size)
{
    const float* coord    = (const float*)d_in[0];
    const float* goal     = (const float*)d_in[1];
    const float* frontier = (const float*)d_in[2];
    const float* rel      = (const float*)d_in[3];
    const int*   adj      = (const int*)d_in[4];
    const float* base     = (const float*)d_in[5];
    const float* gc       = (const float*)d_in[6];
    const float* W1       = (const float*)d_in[7];
    const float* b1       = (const float*)d_in[8];
    const float* W2       = (const float*)d_in[9];
    const float* b2       = (const float*)d_in[10];
    float* out = (float*)d_out;

    precompute_kernel<<<392, 128>>>(coord, goal, frontier, gc, W1, b1);
    dim3 grid(AA / 4, BB);
    edge_kernel<<<grid, 384>>>(rel, adj, base, W1, W2, b2, out);
}